// round 2
// baseline (speedup 1.0000x reference)
#include <cuda_runtime.h>
#include <math.h>

// x: [B=64, S=4096, N=25, F=3] fp32
// out: [B, S, N, 5] fp32 : {x0,x1,x2, dist(x,x_next), angle(x,x_next)}
// x_next = x at s+1 (same b,n), clamped to self at s == S-1.

#define S_      4096
#define N_      25
#define TILE    1024                 // points per block
#define THREADS 256
#define PPT     (TILE / THREADS)     // 4 points per thread
#define IN_VEC  ((TILE * 3 + 75 + 3) / 4)   // 787 float4 (tile + neighbor overhang)

__global__ __launch_bounds__(THREADS) void posenc_kernel(
    const float4* __restrict__ x4,
    float4* __restrict__ o4,
    int n_points)
{
    __shared__ float4 s_in4[IN_VEC];          // 3148 floats
    __shared__ float  s_out[TILE * 5];        // 5120 floats
    float* s_in = (float*)s_in4;

    const int tid       = threadIdx.x;
    const int tile_base = blockIdx.x * TILE;

    // ---- Phase 1: coalesced float4 load of tile + 75-float overhang ----
    const long total_vec = (long)n_points * 3 / 4;          // input floats divisible by 4
    const long base_v    = (long)tile_base * 3 / 4;          // tile_base*3 % 4 == 0

    #pragma unroll
    for (int i = tid; i < IN_VEC; i += THREADS) {
        long gv = base_v + i;
        float4 v = (gv < total_vec) ? __ldcs(&x4[gv]) : make_float4(0.f, 0.f, 0.f, 0.f);
        s_in4[i] = v;
    }
    __syncthreads();

    // ---- Phase 2: compute (stride-3 LDS / stride-5 STS, both conflict-free) ----
    #pragma unroll
    for (int k = 0; k < PPT; k++) {
        int q  = k * THREADS + tid;           // local point index
        int gp = tile_base + q;               // global point index
        if (gp >= n_points) break;

        int s = (gp / N_) & (S_ - 1);         // seq position

        const float* a = &s_in[q * 3];
        const float* b = (s == S_ - 1) ? a : (a + N_ * 3);

        float x0 = a[0], x1 = a[1], x2 = a[2];
        float y0 = b[0], y1 = b[1], y2 = b[2];

        float d0 = y0 - x0, d1 = y1 - x1, d2 = y2 - x2;
        float dist = sqrtf(d0 * d0 + d1 * d1 + d2 * d2);

        float dot = x0 * y0 + x1 * y1 + x2 * y2;
        float la  = sqrtf(x0 * x0 + x1 * x1 + x2 * x2);
        float lb  = sqrtf(y0 * y0 + y1 * y1 + y2 * y2);

        float ang = acosf(dot / (la * lb));
        if (isnan(ang)) ang = 0.0f;           // jnp.nan_to_num

        float* o = &s_out[q * 5];
        o[0] = x0; o[1] = x1; o[2] = x2;
        o[3] = dist; o[4] = ang;
    }
    __syncthreads();

    // ---- Phase 3: coalesced float4 store ----
    const long obase = (long)tile_base * 5 / 4;              // tile_base*5 % 4 == 0
    const long total_ovec = (long)n_points * 5 / 4;

    #pragma unroll
    for (int i = tid; i < TILE * 5 / 4; i += THREADS) {
        long gv = obase + i;
        if (gv < total_ovec)
            __stcs(&o4[gv], *(const float4*)&s_out[i * 4]);
    }
}

extern "C" void kernel_launch(void* const* d_in, const int* in_sizes, int n_in,
                              void* d_out, int out_size)
{
    const float4* x = (const float4*)d_in[0];
    float4* out = (float4*)d_out;

    int n_points = in_sizes[0] / 3;                      // B*S*N = 6,553,600
    int blocks = (n_points + TILE - 1) / TILE;           // 6400

    posenc_kernel<<<blocks, THREADS>>>(x, out, n_points);
}

// round 3
// speedup vs baseline: 1.0409x; 1.0409x over previous
#include <cuda_runtime.h>
#include <math.h>

// x: [B=64, S=4096, N=25, F=3] fp32
// out: [B, S, N, 5] fp32 : {x0,x1,x2, dist(x,x_next), angle(x,x_next)}
// x_next = x at s+1 (same b,n), clamped to self at s == S-1.

#define S_      4096
#define N_      25
#define SEQ     (S_ * N_)            // 102400 points per batch element
#define TILE    1024                 // points per block (n_points = 6400 * TILE exactly)
#define THREADS 256                  // 4 consecutive points per thread
#define IN_VEC  787                  // float4: covers floats [0, 3148) = 12*255+88 max need

__global__ __launch_bounds__(THREADS) void posenc_kernel(
    const float4* __restrict__ x4,
    float4* __restrict__ o4,
    int n_points)
{
    __shared__ float4 s_in4[IN_VEC];           // 12,592 B
    __shared__ float4 s_out4[TILE * 5 / 4];    // 20,480 B

    const int tid       = threadIdx.x;
    const int tile_base = blockIdx.x * TILE;

    // ---- Phase 1: coalesced float4 load of tile + neighbor overhang ----
    const long total_vec = (long)n_points * 3 / 4;
    const long base_v    = (long)tile_base * 3 / 4;   // tile_base*3 % 4 == 0

    #pragma unroll
    for (int i = tid; i < IN_VEC; i += THREADS) {
        long gv = base_v + i;
        s_in4[i] = (gv < total_vec) ? __ldcs(&x4[gv]) : make_float4(0.f, 0.f, 0.f, 0.f);
    }
    __syncthreads();

    // ---- Phase 2: 4 consecutive points per thread, all-vector smem access ----
    {
        // Own floats [12t, 12t+12): 3 x LDS.128
        float4 a0 = s_in4[3 * tid + 0];
        float4 a1 = s_in4[3 * tid + 1];
        float4 a2 = s_in4[3 * tid + 2];
        // Neighbor floats [12t+72, 12t+88): 4 x LDS.128 (covers [12t+75, 12t+87))
        float4 b0 = s_in4[3 * tid + 18];
        float4 b1 = s_in4[3 * tid + 19];
        float4 b2 = s_in4[3 * tid + 20];
        float4 b3 = s_in4[3 * tid + 21];

        float own[12] = { a0.x, a0.y, a0.z, a0.w, a1.x, a1.y, a1.z, a1.w,
                          a2.x, a2.y, a2.z, a2.w };
        float nb[16]  = { b0.x, b0.y, b0.z, b0.w, b1.x, b1.y, b1.z, b1.w,
                          b2.x, b2.y, b2.z, b2.w, b3.x, b3.y, b3.z, b3.w };

        // Sequence-position bookkeeping: one mod per thread.
        // Thread's 4 points are consecutive; batch boundaries (mult of 102400)
        // are 4-aligned, so no wrap inside a thread.
        int r0 = (tile_base + 4 * tid) % SEQ;

        float ob[20];
        #pragma unroll
        for (int k = 0; k < 4; k++) {
            bool is_last = (r0 + k) >= (SEQ - N_);   // s == S_-1

            float x0 = own[3 * k + 0];
            float x1 = own[3 * k + 1];
            float x2 = own[3 * k + 2];
            float y0 = is_last ? x0 : nb[3 * k + 3];
            float y1 = is_last ? x1 : nb[3 * k + 4];
            float y2 = is_last ? x2 : nb[3 * k + 5];

            float d0 = y0 - x0, d1 = y1 - x1, d2 = y2 - x2;
            float dist = sqrtf(d0 * d0 + d1 * d1 + d2 * d2);

            float dot = x0 * y0 + x1 * y1 + x2 * y2;
            float la  = sqrtf(x0 * x0 + x1 * x1 + x2 * x2);
            float lb  = sqrtf(y0 * y0 + y1 * y1 + y2 * y2);

            float ang = acosf(dot / (la * lb));
            if (isnan(ang)) ang = 0.0f;              // jnp.nan_to_num

            ob[5 * k + 0] = x0;
            ob[5 * k + 1] = x1;
            ob[5 * k + 2] = x2;
            ob[5 * k + 3] = dist;
            ob[5 * k + 4] = ang;
        }

        // 20 floats -> 5 x STS.128 at byte 80*tid (16B-aligned, conflict-free)
        float4* dst = &s_out4[5 * tid];
        dst[0] = make_float4(ob[0],  ob[1],  ob[2],  ob[3]);
        dst[1] = make_float4(ob[4],  ob[5],  ob[6],  ob[7]);
        dst[2] = make_float4(ob[8],  ob[9],  ob[10], ob[11]);
        dst[3] = make_float4(ob[12], ob[13], ob[14], ob[15]);
        dst[4] = make_float4(ob[16], ob[17], ob[18], ob[19]);
    }
    __syncthreads();

    // ---- Phase 3: coalesced float4 store (exact: TILE*5/4 = 1280 vectors) ----
    const long obase = (long)tile_base * 5 / 4;
    #pragma unroll
    for (int j = 0; j < TILE * 5 / 4 / THREADS; j++) {
        int i = j * THREADS + tid;
        __stcs(&o4[obase + i], s_out4[i]);
    }
}

extern "C" void kernel_launch(void* const* d_in, const int* in_sizes, int n_in,
                              void* d_out, int out_size)
{
    const float4* x = (const float4*)d_in[0];
    float4* out = (float4*)d_out;

    int n_points = in_sizes[0] / 3;              // 6,553,600 = 6400 * 1024
    int blocks = n_points / TILE;                // 6400 (exact)

    posenc_kernel<<<blocks, THREADS>>>(x, out, n_points);
}

// round 4
// speedup vs baseline: 1.0871x; 1.0444x over previous
#include <cuda_runtime.h>
#include <math.h>
#include <stdint.h>

// x: [B=64, S=4096, N=25, F=3] fp32
// out: [B, S, N, 5] fp32 : {x0,x1,x2, dist(x,x_next), angle(x,x_next)}
// x_next = x at s+1 (same b,n), clamped to self at s == S-1.

#define S_      4096
#define N_      25
#define SEQ     (S_ * N_)            // 102400 points per batch element (1024-aligned)
#define TILE    1024                 // points per block; n_points = 6400 * TILE exactly
#define THREADS 256                  // 4 consecutive points per thread
#define IN_VEC  787                  // float4 slots: floats [0, 3148) = tile 3072 + overhang
#define IN_BYTES_FULL (IN_VEC * 16)  // 12592
#define OUT_VEC (TILE * 5 / 4)       // 1280
#define OUT_BYTES (OUT_VEC * 16)     // 20480

__device__ __forceinline__ uint32_t smem_u32(const void* p) {
    uint32_t a;
    asm("{ .reg .u64 t; cvta.to.shared.u64 t, %1; cvt.u32.u64 %0, t; }" : "=r"(a) : "l"(p));
    return a;
}

__global__ __launch_bounds__(THREADS) void posenc_kernel(
    const float* __restrict__ x,
    float* __restrict__ out,
    int total_vec)                    // total float4 count of input
{
    __shared__ float4 s_in4[IN_VEC];             // 12,592 B
    __shared__ float4 s_out4[OUT_VEC];           // 20,480 B
    __shared__ alignas(8) uint64_t mbar;

    const int tid       = threadIdx.x;
    const int tile_base = blockIdx.x * TILE;

    const uint32_t mbar_a  = smem_u32(&mbar);
    const uint32_t s_in_a  = smem_u32(s_in4);
    const uint32_t s_out_a = smem_u32(s_out4);

    // ---- Phase 1: bulk-async copy gmem -> smem ----
    if (tid == 0) {
        asm volatile("mbarrier.init.shared.b64 [%0], 1;" :: "r"(mbar_a) : "memory");
    }
    __syncthreads();

    if (tid == 0) {
        long base_v = (long)tile_base * 3 / 4;                // 16B-aligned source
        long rem_bytes = ((long)total_vec - base_v) * 16;
        uint32_t nbytes = (rem_bytes < IN_BYTES_FULL) ? (uint32_t)rem_bytes
                                                      : (uint32_t)IN_BYTES_FULL;
        asm volatile("mbarrier.arrive.expect_tx.shared.b64 _, [%0], %1;"
                     :: "r"(mbar_a), "r"(nbytes) : "memory");
        asm volatile("cp.async.bulk.shared::cluster.global.mbarrier::complete_tx::bytes"
                     " [%0], [%1], %2, [%3];"
                     :: "r"(s_in_a), "l"(x + base_v * 4), "r"(nbytes), "r"(mbar_a)
                     : "memory");
    }

    // Wait (parity 0: single-shot barrier)
    {
        asm volatile(
            "{\n\t"
            ".reg .pred P;\n\t"
            "WAIT_%=:\n\t"
            "mbarrier.try_wait.parity.acquire.cta.shared::cta.b64 P, [%0], 0, 0x989680;\n\t"
            "@P bra.uni DONE_%=;\n\t"
            "bra.uni WAIT_%=;\n\t"
            "DONE_%=:\n\t"
            "}" :: "r"(mbar_a) : "memory");
    }

    // ---- Phase 2: 4 consecutive points per thread, all-vector smem access ----
    {
        // Own floats [12t, 12t+12): 3 x LDS.128
        float4 a0 = s_in4[3 * tid + 0];
        float4 a1 = s_in4[3 * tid + 1];
        float4 a2 = s_in4[3 * tid + 2];
        // Neighbor floats [12t+72, 12t+88): 4 x LDS.128 (covers [12t+75, 12t+87))
        float4 b0 = s_in4[3 * tid + 18];
        float4 b1 = s_in4[3 * tid + 19];
        float4 b2 = s_in4[3 * tid + 20];
        float4 b3 = s_in4[3 * tid + 21];

        float own[12] = { a0.x, a0.y, a0.z, a0.w, a1.x, a1.y, a1.z, a1.w,
                          a2.x, a2.y, a2.z, a2.w };
        float nb[16]  = { b0.x, b0.y, b0.z, b0.w, b1.x, b1.y, b1.z, b1.w,
                          b2.x, b2.y, b2.z, b2.w, b3.x, b3.y, b3.z, b3.w };

        // Tiles never cross batch boundaries (SEQ = 100 * TILE).
        int r0 = (tile_base + 4 * tid) % SEQ;

        float ob[20];
        #pragma unroll
        for (int k = 0; k < 4; k++) {
            bool is_last = (r0 + k) >= (SEQ - N_);   // s == S_-1 -> neighbor = self

            float x0 = own[3 * k + 0];
            float x1 = own[3 * k + 1];
            float x2 = own[3 * k + 2];
            float y0 = is_last ? x0 : nb[3 * k + 3];
            float y1 = is_last ? x1 : nb[3 * k + 4];
            float y2 = is_last ? x2 : nb[3 * k + 5];

            float d0 = y0 - x0, d1 = y1 - x1, d2 = y2 - x2;
            float dist = sqrtf(d0 * d0 + d1 * d1 + d2 * d2);

            float dot = x0 * y0 + x1 * y1 + x2 * y2;
            float la  = sqrtf(x0 * x0 + x1 * x1 + x2 * x2);
            float lb  = sqrtf(y0 * y0 + y1 * y1 + y2 * y2);

            float ang = acosf(dot / (la * lb));
            if (isnan(ang)) ang = 0.0f;              // jnp.nan_to_num

            ob[5 * k + 0] = x0;
            ob[5 * k + 1] = x1;
            ob[5 * k + 2] = x2;
            ob[5 * k + 3] = dist;
            ob[5 * k + 4] = ang;
        }

        // 20 floats -> 5 x STS.128 at byte 80*tid (16B-aligned, conflict-free)
        float4* dst = &s_out4[5 * tid];
        dst[0] = make_float4(ob[0],  ob[1],  ob[2],  ob[3]);
        dst[1] = make_float4(ob[4],  ob[5],  ob[6],  ob[7]);
        dst[2] = make_float4(ob[8],  ob[9],  ob[10], ob[11]);
        dst[3] = make_float4(ob[12], ob[13], ob[14], ob[15]);
        dst[4] = make_float4(ob[16], ob[17], ob[18], ob[19]);
    }
    __syncthreads();

    // ---- Phase 3: bulk-async copy smem -> gmem (20 KB contiguous) ----
    if (tid == 0) {
        asm volatile("fence.proxy.async.shared::cta;" ::: "memory");
        float* gdst = out + (long)tile_base * 5;
        asm volatile("cp.async.bulk.global.shared::cta.bulk_group [%0], [%1], %2;"
                     :: "l"(gdst), "r"(s_out_a), "r"((uint32_t)OUT_BYTES) : "memory");
        asm volatile("cp.async.bulk.commit_group;" ::: "memory");
        asm volatile("cp.async.bulk.wait_group.read 0;" ::: "memory");
    }
}

extern "C" void kernel_launch(void* const* d_in, const int* in_sizes, int n_in,
                              void* d_out, int out_size)
{
    const float* x = (const float*)d_in[0];
    float* out = (float*)d_out;

    int n_points  = in_sizes[0] / 3;          // 6,553,600 = 6400 * TILE exactly
    int total_vec = in_sizes[0] / 4;          // input float4 count
    int blocks    = n_points / TILE;          // 6400

    posenc_kernel<<<blocks, THREADS>>>(x, out, total_vec);
}

// round 5
// speedup vs baseline: 1.1521x; 1.0598x over previous
#include <cuda_runtime.h>
#include <math.h>
#include <stdint.h>

// x: [B=64, S=4096, N=25, F=3] fp32
// out: [B, S, N, 5] fp32 : {x0,x1,x2, dist(x,x_next), angle(x,x_next)}
// x_next = x at s+1 (same b,n), clamped to self at s == S-1.

#define S_        4096
#define N_        25
#define SEQ       (S_ * N_)          // 102400 points per batch element
#define TILE      1024               // points per tile
#define THREADS   256                // 4 consecutive points per thread
#define PIPE      3                  // input pipeline depth
#define OUTB      2                  // output double-buffer
#define IN_BYTES  12592              // 787 float4 = tile(3072 fl) + overhang(76 fl)
#define IN_STRIDE 12608              // 16B-aligned stage stride
#define OUT_BYTES 20480              // 1280 float4
#define IN_OFF    0
#define OUT_OFF   (PIPE * IN_STRIDE)               // 37824
#define MBAR_OFF  (OUT_OFF + OUTB * OUT_BYTES)     // 78784
#define SMEM_TOTAL (MBAR_OFF + PIPE * 8)           // 78808

__device__ __forceinline__ uint32_t smem_u32(const void* p) {
    uint32_t a;
    asm("{ .reg .u64 t; cvta.to.shared.u64 t, %1; cvt.u32.u64 %0, t; }" : "=r"(a) : "l"(p));
    return a;
}

__device__ __forceinline__ void mbar_wait(uint32_t mbar_a, int parity) {
    asm volatile(
        "{\n\t"
        ".reg .pred P;\n\t"
        "WAIT_%=:\n\t"
        "mbarrier.try_wait.parity.acquire.cta.shared::cta.b64 P, [%0], %1, 0x989680;\n\t"
        "@P bra.uni DONE_%=;\n\t"
        "bra.uni WAIT_%=;\n\t"
        "DONE_%=:\n\t"
        "}" :: "r"(mbar_a), "r"(parity) : "memory");
}

__device__ __forceinline__ void issue_load(uint32_t dst_a, uint32_t mbar_a,
                                           const float* __restrict__ x,
                                           long tile, long total_vec) {
    long base_v = tile * 768;                       // tile*3072 floats / 4
    long rem    = (total_vec - base_v) * 16;
    uint32_t nbytes = (rem < (long)IN_BYTES) ? (uint32_t)rem : (uint32_t)IN_BYTES;
    asm volatile("mbarrier.arrive.expect_tx.shared.b64 _, [%0], %1;"
                 :: "r"(mbar_a), "r"(nbytes) : "memory");
    asm volatile("cp.async.bulk.shared::cluster.global.mbarrier::complete_tx::bytes"
                 " [%0], [%1], %2, [%3];"
                 :: "r"(dst_a), "l"(x + base_v * 4), "r"(nbytes), "r"(mbar_a)
                 : "memory");
}

__global__ __launch_bounds__(THREADS) void posenc_kernel(
    const float* __restrict__ x,
    float* __restrict__ out,
    int n_tiles, int total_vec)
{
    extern __shared__ char smem[];

    const int tid  = threadIdx.x;
    const int bid  = blockIdx.x;
    const int gdim = gridDim.x;

    const uint32_t smem_a = smem_u32(smem);

    // Per-CTA tile list: t = bid + k*gdim, k = 0..ntiles-1
    const int ntiles = (n_tiles - bid + gdim - 1) / gdim;
    if (ntiles <= 0) return;

    // ---- init barriers + prologue loads ----
    if (tid == 0) {
        #pragma unroll
        for (int p = 0; p < PIPE; p++)
            asm volatile("mbarrier.init.shared.b64 [%0], 1;"
                         :: "r"(smem_a + MBAR_OFF + p * 8) : "memory");
        asm volatile("fence.proxy.async.shared::cta;" ::: "memory");
        int npro = ntiles < PIPE ? ntiles : PIPE;
        for (int p = 0; p < npro; p++)
            issue_load(smem_a + IN_OFF + p * IN_STRIDE,
                       smem_a + MBAR_OFF + p * 8,
                       x, (long)bid + (long)p * gdim, total_vec);
    }
    __syncthreads();

    int stage = 0, parity = 0;

    for (int k = 0; k < ntiles; k++) {
        const long t = (long)bid + (long)k * gdim;
        const int  tile_base = (int)t * TILE;
        const float4* s_in4 = (const float4*)(smem + IN_OFF + stage * IN_STRIDE);

        // wait for this stage's data
        mbar_wait(smem_a + MBAR_OFF + stage * 8, parity);

        // ---- read inputs (all LDS.128, conflict-free) ----
        float4 a0 = s_in4[3 * tid + 0];
        float4 a1 = s_in4[3 * tid + 1];
        float4 a2 = s_in4[3 * tid + 2];
        float4 b0 = s_in4[3 * tid + 18];
        float4 b1 = s_in4[3 * tid + 19];
        float4 b2 = s_in4[3 * tid + 20];
        float4 b3 = s_in4[3 * tid + 21];

        __syncthreads();   // all reads of in[stage] complete

        // refill this stage for tile k+PIPE
        if (tid == 0 && k + PIPE < ntiles)
            issue_load(smem_a + IN_OFF + stage * IN_STRIDE,
                       smem_a + MBAR_OFF + stage * 8,
                       x, t + (long)PIPE * gdim, total_vec);

        // ---- compute 4 points ----
        float own[12] = { a0.x, a0.y, a0.z, a0.w, a1.x, a1.y, a1.z, a1.w,
                          a2.x, a2.y, a2.z, a2.w };
        float nb[16]  = { b0.x, b0.y, b0.z, b0.w, b1.x, b1.y, b1.z, b1.w,
                          b2.x, b2.y, b2.z, b2.w, b3.x, b3.y, b3.z, b3.w };

        int r0 = (tile_base + 4 * tid) % SEQ;

        float ob[20];
        #pragma unroll
        for (int q = 0; q < 4; q++) {
            bool is_last = (r0 + q) >= (SEQ - N_);   // s == S_-1 -> neighbor = self

            float x0 = own[3 * q + 0];
            float x1 = own[3 * q + 1];
            float x2 = own[3 * q + 2];
            float y0 = is_last ? x0 : nb[3 * q + 3];
            float y1 = is_last ? x1 : nb[3 * q + 4];
            float y2 = is_last ? x2 : nb[3 * q + 5];

            float d0 = y0 - x0, d1 = y1 - x1, d2 = y2 - x2;
            float dist = sqrtf(d0 * d0 + d1 * d1 + d2 * d2);

            float dot = x0 * y0 + x1 * y1 + x2 * y2;
            float la  = sqrtf(x0 * x0 + x1 * x1 + x2 * x2);
            float lb  = sqrtf(y0 * y0 + y1 * y1 + y2 * y2);

            float ang = acosf(dot / (la * lb));
            if (isnan(ang)) ang = 0.0f;              // jnp.nan_to_num

            ob[5 * q + 0] = x0;
            ob[5 * q + 1] = x1;
            ob[5 * q + 2] = x2;
            ob[5 * q + 3] = dist;
            ob[5 * q + 4] = ang;
        }

        // ---- out buffer backpressure: at most 1 outstanding store group ----
        if (tid == 0)
            asm volatile("cp.async.bulk.wait_group.read 1;" ::: "memory");
        __syncthreads();

        float4* s_out4 = (float4*)(smem + OUT_OFF + (k & 1) * OUT_BYTES);
        float4* dst = &s_out4[5 * tid];
        dst[0] = make_float4(ob[0],  ob[1],  ob[2],  ob[3]);
        dst[1] = make_float4(ob[4],  ob[5],  ob[6],  ob[7]);
        dst[2] = make_float4(ob[8],  ob[9],  ob[10], ob[11]);
        dst[3] = make_float4(ob[12], ob[13], ob[14], ob[15]);
        dst[4] = make_float4(ob[16], ob[17], ob[18], ob[19]);
        __syncthreads();

        if (tid == 0) {
            asm volatile("fence.proxy.async.shared::cta;" ::: "memory");
            float* gdst = out + t * (TILE * 5);
            asm volatile("cp.async.bulk.global.shared::cta.bulk_group [%0], [%1], %2;"
                         :: "l"(gdst),
                            "r"(smem_a + OUT_OFF + (uint32_t)((k & 1) * OUT_BYTES)),
                            "r"((uint32_t)OUT_BYTES) : "memory");
            asm volatile("cp.async.bulk.commit_group;" ::: "memory");
        }

        if (++stage == PIPE) { stage = 0; parity ^= 1; }
    }

    // drain outstanding stores before smem is invalidated by CTA exit
    if (tid == 0)
        asm volatile("cp.async.bulk.wait_group.read 0;" ::: "memory");
    __syncthreads();
}

extern "C" void kernel_launch(void* const* d_in, const int* in_sizes, int n_in,
                              void* d_out, int out_size)
{
    const float* x = (const float*)d_in[0];
    float* out = (float*)d_out;

    int n_points  = in_sizes[0] / 3;          // 6,553,600 = 6400 * TILE exactly
    int n_tiles   = n_points / TILE;          // 6400
    int total_vec = in_sizes[0] / 4;          // input float4 count

    static int smem_set = 0;
    if (!smem_set) {
        cudaFuncSetAttribute(posenc_kernel,
                             cudaFuncAttributeMaxDynamicSharedMemorySize, SMEM_TOTAL);
        smem_set = 1;
    }

    int blocks = 304;                          // 2 persistent CTAs per SM (152 SMs)
    posenc_kernel<<<blocks, THREADS, SMEM_TOTAL>>>(x, out, n_tiles, total_vec);
}